// round 4
// baseline (speedup 1.0000x reference)
#include <cuda_runtime.h>

typedef unsigned long long U64;

// ---------------- static device scratch ----------------
__device__ float g_xp[16777216];   // [2][64][1024][128] gate pre-activations (reused per layer)
__device__ float g_h0[4194304];    // [64][1024][64] layer0 out (fwd|bwd)
__device__ float g_h1[4194304];    // [64][1024][64] layer1 out
__device__ float g_part1[4194304]; // [32][64][2048] fc1 split-K partials
__device__ float g_hidden[131072]; // [64][2048]
__device__ float g_part2[1179648]; // [2][64][9216] fc2 split-K partials

// ---------------- helpers ----------------
__device__ __forceinline__ void ffma2(U64 &acc, U64 a, U64 b){
    asm("fma.rn.f32x2 %0, %1, %2, %0;" : "+l"(acc) : "l"(a), "l"(b));
}
__device__ __forceinline__ float2 unpk(U64 v){
    float2 r; asm("mov.b64 {%0, %1}, %2;" : "=f"(r.x), "=f"(r.y) : "l"(v)); return r;
}
__device__ __forceinline__ float sum2(U64 v){ float2 r = unpk(v); return r.x + r.y; }
__device__ __forceinline__ float fex2(float x){ float r; asm("ex2.approx.ftz.f32 %0, %1;" : "=f"(r) : "f"(x)); return r; }
__device__ __forceinline__ float frcp(float x){ float r; asm("rcp.approx.ftz.f32 %0, %1;" : "=f"(r) : "f"(x)); return r; }
__device__ __forceinline__ float sigf (float x){ return frcp(1.0f + fex2(-1.4426950408889634f * x)); }
__device__ __forceinline__ float tanhx(float x){ return fmaf(-2.0f, frcp(1.0f + fex2(2.8853900817779268f * x)), 1.0f); }

// ---------------- xproj layer 0 (K=9) ----------------
__global__ void xproj0_kernel(const float* __restrict__ x,
    const float* __restrict__ wf, const float* __restrict__ bif, const float* __restrict__ bhf,
    const float* __restrict__ wr, const float* __restrict__ bir, const float* __restrict__ bhr)
{
    int idx = blockIdx.x * 256 + threadIdx.x;   // 16,777,216 total
    int j = idx & 127;
    int s = (idx >> 7) & 1023;
    int b = (idx >> 17) & 63;
    int d = idx >> 23;
    const float* w = d ? wr : wf;
    float acc = d ? (bir[j] + bhr[j]) : (bif[j] + bhf[j]);
    int tsrc = d ? (1023 - s) : s;
    const float* xr = x + ((size_t)b * 1024 + tsrc) * 9;
    const float* wrow = w + j * 9;
    #pragma unroll
    for (int k = 0; k < 9; k++) acc = fmaf(xr[k], wrow[k], acc);
    g_xp[idx] = acc;
}

// ---------------- xproj layer 1 (K=64, f32x2) ----------------
__global__ void xproj1_kernel(
    const float* __restrict__ wf, const float* __restrict__ bif, const float* __restrict__ bhf,
    const float* __restrict__ wr, const float* __restrict__ bir, const float* __restrict__ bhr)
{
    int idx = blockIdx.x * 256 + threadIdx.x;
    int j = idx & 127;
    int s = (idx >> 7) & 1023;
    int b = (idx >> 17) & 63;
    int d = idx >> 23;
    const float* w = d ? wr : wf;
    float bias = d ? (bir[j] + bhr[j]) : (bif[j] + bhf[j]);
    int tsrc = d ? (1023 - s) : s;
    const ulonglong2* hp = (const ulonglong2*)(g_h0 + ((size_t)b * 1024 + tsrc) * 64);
    const ulonglong2* wp = (const ulonglong2*)(w + j * 64);
    U64 acc = 0ull;
    #pragma unroll
    for (int r = 0; r < 16; r++){
        ulonglong2 hv = hp[r];
        ulonglong2 wv = wp[r];
        ffma2(acc, hv.x, wv.x);
        ffma2(acc, hv.y, wv.y);
    }
    g_xp[idx] = bias + sum2(acc);
}

// ---------------- LSTM recurrence: 1 warp per (dir, batch) ----------------
__global__ void __launch_bounds__(32, 1) lstm_kernel(
    const float* __restrict__ whh_f, const float* __restrict__ whh_r, int outsel)
{
    const int blk = blockIdx.x;          // 0..127
    const int d = blk >> 6, b = blk & 63;
    const int hh = threadIdx.x;          // 0..31
    float* hout = outsel ? g_h1 : g_h0;
    const float* whh = d ? whh_r : whh_f;

    U64 wp[4][16];                        // Whh rows for this lane's 4 gates, as f32x2 pairs
    #pragma unroll
    for (int g = 0; g < 4; g++){
        const ulonglong2* wr2 = (const ulonglong2*)(whh + (g * 32 + hh) * 32);
        #pragma unroll
        for (int r = 0; r < 8; r++){ ulonglong2 v = wr2[r]; wp[g][2*r] = v.x; wp[g][2*r+1] = v.y; }
    }

    __shared__ __align__(16) float hs[32];
    hs[hh] = 0.0f;
    float c = 0.0f;
    __syncwarp();

    const float* xb = g_xp + (size_t)(d * 64 + b) * 1024 * 128;
    float a0 = xb[hh],     a1 = xb[32 + hh], a2 = xb[64 + hh], a3 = xb[96 + hh];
    const float* q1 = xb + 128;
    float p0 = q1[hh],     p1 = q1[32 + hh], p2 = q1[64 + hh], p3 = q1[96 + hh];

    float* outp = hout + (size_t)b * 1024 * 64 + d * 32 + hh;

    for (int s = 0; s < 1024; s++){
        float n0 = 0.f, n1 = 0.f, n2 = 0.f, n3 = 0.f;
        if (s + 2 < 1024){
            const float* q = xb + (size_t)(s + 2) * 128;
            n0 = q[hh]; n1 = q[32 + hh]; n2 = q[64 + hh]; n3 = q[96 + hh];
        }
        U64 acc0 = 0ull, acc1 = 0ull, acc2 = 0ull, acc3 = 0ull;
        const ulonglong2* h2 = (const ulonglong2*)hs;
        #pragma unroll
        for (int r = 0; r < 8; r++){
            ulonglong2 hv = h2[r];
            ffma2(acc0, hv.x, wp[0][2*r]); ffma2(acc0, hv.y, wp[0][2*r+1]);
            ffma2(acc1, hv.x, wp[1][2*r]); ffma2(acc1, hv.y, wp[1][2*r+1]);
            ffma2(acc2, hv.x, wp[2][2*r]); ffma2(acc2, hv.y, wp[2][2*r+1]);
            ffma2(acc3, hv.x, wp[3][2*r]); ffma2(acc3, hv.y, wp[3][2*r+1]);
        }
        float iv = sigf (a0 + sum2(acc0));
        float fv = sigf (a1 + sum2(acc1));
        float gv = tanhx(a2 + sum2(acc2));
        float ov = sigf (a3 + sum2(acc3));
        c = fmaf(fv, c, iv * gv);
        float hval = ov * tanhx(c);

        __syncwarp();                     // all lanes done READING hs before anyone writes
        hs[hh] = hval;
        int tout = d ? (1023 - s) : s;
        outp[(size_t)tout * 64] = hval;

        a0 = p0; a1 = p1; a2 = p2; a3 = p3;
        p0 = n0; p1 = n1; p2 = n2; p3 = n3;
        __syncwarp();                     // hs visible before next step's reads
    }
}

// ---------------- f32x2 GEMM w/ split-K: part[split][64][N] = X[64][K] @ W[N][K]^T ----------------
#define FC_NK 32
#define FC_WS 132

__global__ void __launch_bounds__(128) fc_kernel(
    const float* __restrict__ W, int sel, int N, int K, int kPerSplit)
{
    const float* __restrict__ X = sel ? g_hidden : g_h1;
    float* __restrict__ part = sel ? g_part2 : g_part1;

    __shared__ float ws[FC_NK * FC_WS];   // W tile transposed: ws[k][m]
    __shared__ float fs[FC_NK * FC_WS];   // X tile duplicated: fs[k][2b]=fs[k][2b+1]=X[b][k]

    const int tid = threadIdx.x;
    const int mi = tid & 15;              // 16 m-groups of 8
    const int bi = tid >> 4;              // 8 b-groups of 8
    const int mbase = blockIdx.x * 128;
    const int kstart = blockIdx.y * kPerSplit;

    U64 acc[8][4];
    #pragma unroll
    for (int i = 0; i < 8; i++)
        #pragma unroll
        for (int jj = 0; jj < 4; jj++) acc[i][jj] = 0ull;

    const int nchunk = kPerSplit / FC_NK;
    for (int ch = 0; ch < nchunk; ch++){
        int k0 = kstart + ch * FC_NK;
        #pragma unroll
        for (int it = 0; it < 8; it++){   // W tile: 128m x 32k
            int i = it * 128 + tid;
            int mL = i >> 3, k4 = i & 7;
            float4 v = *(const float4*)(W + (size_t)(mbase + mL) * K + k0 + k4 * 4);
            int c0 = k4 * 4;
            ws[(c0 + 0) * FC_WS + mL] = v.x;
            ws[(c0 + 1) * FC_WS + mL] = v.y;
            ws[(c0 + 2) * FC_WS + mL] = v.z;
            ws[(c0 + 3) * FC_WS + mL] = v.w;
        }
        #pragma unroll
        for (int it = 0; it < 4; it++){   // X tile: 64b x 32k, duplicated
            int i = it * 128 + tid;
            int bL = i >> 3, k4 = i & 7;
            float4 v = *(const float4*)(X + (size_t)bL * K + k0 + k4 * 4);
            int c0 = k4 * 4;
            fs[(c0 + 0) * FC_WS + 2*bL] = v.x; fs[(c0 + 0) * FC_WS + 2*bL + 1] = v.x;
            fs[(c0 + 1) * FC_WS + 2*bL] = v.y; fs[(c0 + 1) * FC_WS + 2*bL + 1] = v.y;
            fs[(c0 + 2) * FC_WS + 2*bL] = v.z; fs[(c0 + 2) * FC_WS + 2*bL + 1] = v.z;
            fs[(c0 + 3) * FC_WS + 2*bL] = v.w; fs[(c0 + 3) * FC_WS + 2*bL + 1] = v.w;
        }
        __syncthreads();
        #pragma unroll
        for (int kk = 0; kk < FC_NK; kk++){
            const ulonglong2* wrow = (const ulonglong2*)&ws[kk * FC_WS + mi * 8];
            ulonglong2 w0 = wrow[0], w1 = wrow[1];
            const ulonglong2* frow = (const ulonglong2*)&fs[kk * FC_WS + bi * 16];
            ulonglong2 f0 = frow[0], f1 = frow[1], f2 = frow[2], f3 = frow[3];
            U64 fv[8] = {f0.x, f0.y, f1.x, f1.y, f2.x, f2.y, f3.x, f3.y};
            U64 wv[4] = {w0.x, w0.y, w1.x, w1.y};
            #pragma unroll
            for (int bb = 0; bb < 8; bb++)
                #pragma unroll
                for (int mp = 0; mp < 4; mp++)
                    ffma2(acc[bb][mp], fv[bb], wv[mp]);
        }
        __syncthreads();
    }

    #pragma unroll
    for (int bb = 0; bb < 8; bb++){
        int b = bi * 8 + bb;
        float* dst = part + ((size_t)blockIdx.y * 64 + b) * N + mbase + mi * 8;
        #pragma unroll
        for (int mp = 0; mp < 4; mp++){
            float2 v = unpk(acc[bb][mp]);
            *(float2*)(dst + 2 * mp) = v;
        }
    }
}

// ---------------- split-K reductions ----------------
__global__ void reduce1_kernel(const float* __restrict__ bias){
    int i = blockIdx.x * 256 + threadIdx.x;   // 131072
    int m = i & 2047, b = i >> 11;
    float acc = bias[m];
    #pragma unroll
    for (int s = 0; s < 32; s++) acc += g_part1[((size_t)s * 64 + b) * 2048 + m];
    g_hidden[i] = fmaxf(acc, 0.0f);
}

__global__ void reduce2_kernel(const float* __restrict__ bias, float* __restrict__ out){
    int i = blockIdx.x * 256 + threadIdx.x;   // 589824
    int n = i % 9216, b = i / 9216;
    out[i] = bias[n]
           + g_part2[(size_t)b * 9216 + n]
           + g_part2[(size_t)(64 + b) * 9216 + n];
}

// ---------------- launcher ----------------
extern "C" void kernel_launch(void* const* d_in, const int* in_sizes, int n_in,
                              void* d_out, int out_size)
{
    const float* x     = (const float*)d_in[0];
    const float* wih0  = (const float*)d_in[1];
    const float* whh0  = (const float*)d_in[2];
    const float* bih0  = (const float*)d_in[3];
    const float* bhh0  = (const float*)d_in[4];
    const float* wih0r = (const float*)d_in[5];
    const float* whh0r = (const float*)d_in[6];
    const float* bih0r = (const float*)d_in[7];
    const float* bhh0r = (const float*)d_in[8];
    const float* wih1  = (const float*)d_in[9];
    const float* whh1  = (const float*)d_in[10];
    const float* bih1  = (const float*)d_in[11];
    const float* bhh1  = (const float*)d_in[12];
    const float* wih1r = (const float*)d_in[13];
    const float* whh1r = (const float*)d_in[14];
    const float* bih1r = (const float*)d_in[15];
    const float* bhh1r = (const float*)d_in[16];
    const float* fc1w  = (const float*)d_in[17];
    const float* fc1b  = (const float*)d_in[18];
    const float* fc2w  = (const float*)d_in[19];
    const float* fc2b  = (const float*)d_in[20];
    float* out = (float*)d_out;

    xproj0_kernel<<<65536, 256>>>(x, wih0, bih0, bhh0, wih0r, bih0r, bhh0r);
    lstm_kernel<<<128, 32>>>(whh0, whh0r, 0);
    xproj1_kernel<<<65536, 256>>>(wih1, bih1, bhh1, wih1r, bih1r, bhh1r);
    lstm_kernel<<<128, 32>>>(whh1, whh1r, 1);

    // fc1: N=2048, K=65536, split-K=32 (kPerSplit=2048) -> grid (16, 32)
    fc_kernel<<<dim3(16, 32), 128>>>(fc1w, 0, 2048, 65536, 2048);
    reduce1_kernel<<<512, 256>>>(fc1b);

    // fc2: N=9216, K=2048, split-K=2 (kPerSplit=1024) -> grid (72, 2)
    fc_kernel<<<dim3(72, 2), 128>>>(fc2w, 1, 9216, 2048, 1024);
    reduce2_kernel<<<2304, 256>>>(fc2b, out);
}